// round 1
// baseline (speedup 1.0000x reference)
#include <cuda_runtime.h>
#include <stdint.h>

// Problem shape is fixed: 32 images, 512x512, 1 channel, float32.
#define NIMG 32
#define H    512
#define WPX  512
#define WPR  16                       // 32-bit words per row (512/32)
#define NWORDS (NIMG * H * WPR)       // 262144 words = 1 MB per buffer

// Ping-pong bit buffers (device globals: no allocation allowed).
__device__ uint32_t g_bufA[NWORDS];
__device__ uint32_t g_bufB[NWORDS];

// ---------------------------------------------------------------------------
// Pack: threshold float image to bits. One thread per pixel, warp ballot
// produces one 32-bit word (bit i of word = column base+i). Fully coalesced.
// ---------------------------------------------------------------------------
__global__ void pack_kernel(const float* __restrict__ in) {
    int tid = blockIdx.x * blockDim.x + threadIdx.x;   // pixel index
    float v = in[tid];
    unsigned m = __ballot_sync(0xffffffffu, v >= 0.5f);
    if ((tid & 31) == 0) g_bufA[tid >> 5] = m;
}

__device__ __forceinline__ uint32_t maj3(uint32_t a, uint32_t b, uint32_t c) {
    return (a & b) | (c & (a | b));    // 1 LOP3
}

// ---------------------------------------------------------------------------
// One Zhang-Suen substep on the bit-packed image.
// Thread handles 4 consecutive words (one quarter row): uint4 loads/stores,
// internal word neighbors stay in registers.
//
// Neighbor masks via funnel shifts:
//   east (col+1): (x >> 1) | (next << 31) = __funnelshift_r(x, next, 1)
//   west (col-1): (x << 1) | (prev >> 31) = __funnelshift_l(prev, x, 1)
// Out-of-image neighbors are 0 (matches jnp.pad).
//
// Counts via CSA trees (XOR3 + MAJ3 per full adder):
//   bcnt = P2..P9:      count = S0 + 2*(C1+S1) + 4*C2
//     ge2 = C1|S1|C2,   ge7 = C2 & ((C1&S1) | ((C1^S1)&S0)), le6 = ~ge7
//   acnt = transitions: count = A0 + 2*A1 + 2*(aca+acb+acc)
//     ex1 = A0 & ~(A1|aca|acb|acc)
//   c1&c2 (first):  ~((P4&P6)&(P2|P8));  (second): ~((P2&P8)&(P4|P6))
// ---------------------------------------------------------------------------
template<bool FIRST, bool SRC_A>
__global__ void substep_kernel() {
    const uint32_t* __restrict__ src = SRC_A ? g_bufA : g_bufB;
    uint32_t* __restrict__ dst       = SRC_A ? g_bufB : g_bufA;

    int tid = blockIdx.x * blockDim.x + threadIdx.x;   // 0 .. 65535
    int quarter = tid & 3;                             // which 4-word group
    int rowg    = tid >> 2;                            // img*512 + row
    int row     = rowg & (H - 1);
    int base    = rowg * WPR + quarter * 4;

    uint4 um, mm, dm;
    uint32_t ul, ur, ml, mr, dl, dr;

    mm = *(const uint4*)(src + base);
    ml = (quarter > 0) ? src[base - 1] : 0u;
    mr = (quarter < 3) ? src[base + 4] : 0u;

    if (row > 0) {
        um = *(const uint4*)(src + base - WPR);
        ul = (quarter > 0) ? src[base - WPR - 1] : 0u;
        ur = (quarter < 3) ? src[base - WPR + 4] : 0u;
    } else { um = make_uint4(0,0,0,0); ul = ur = 0u; }

    if (row < H - 1) {
        dm = *(const uint4*)(src + base + WPR);
        dl = (quarter > 0) ? src[base + WPR - 1] : 0u;
        dr = (quarter < 3) ? src[base + WPR + 4] : 0u;
    } else { dm = make_uint4(0,0,0,0); dl = dr = 0u; }

    uint32_t u[4] = {um.x, um.y, um.z, um.w};
    uint32_t m[4] = {mm.x, mm.y, mm.z, mm.w};
    uint32_t d[4] = {dm.x, dm.y, dm.z, dm.w};
    uint32_t o[4];

    #pragma unroll
    for (int j = 0; j < 4; ++j) {
        uint32_t up = u[j], mi = m[j], dn = d[j];
        uint32_t upl = j ? u[j-1] : ul, upr = (j < 3) ? u[j+1] : ur;
        uint32_t mil = j ? m[j-1] : ml, mir = (j < 3) ? m[j+1] : mr;
        uint32_t dnl = j ? d[j-1] : dl, dnr = (j < 3) ? d[j+1] : dr;

        uint32_t P2 = up;
        uint32_t P3 = __funnelshift_r(up, upr, 1);
        uint32_t P4 = __funnelshift_r(mi, mir, 1);
        uint32_t P5 = __funnelshift_r(dn, dnr, 1);
        uint32_t P6 = dn;
        uint32_t P7 = __funnelshift_l(dnl, dn, 1);
        uint32_t P8 = __funnelshift_l(mil, mi, 1);
        uint32_t P9 = __funnelshift_l(upl, up, 1);

        // ---- bcnt (8 neighbors) via CSA ----
        uint32_t sa = P2 ^ P3 ^ P4, ca = maj3(P2, P3, P4);
        uint32_t sb = P5 ^ P6 ^ P7, cb = maj3(P5, P6, P7);
        uint32_t sc = P8 ^ P9,      cc = P8 & P9;
        uint32_t S0 = sa ^ sb ^ sc, C1 = maj3(sa, sb, sc);
        uint32_t S1 = ca ^ cb ^ cc, C2 = maj3(ca, cb, cc);
        uint32_t ge2 = C1 | S1 | C2;
        uint32_t ge7 = C2 & ((C1 & S1) | ((C1 ^ S1) & S0));

        // ---- acnt (0->1 transitions around the ring) ----
        uint32_t t0 = ~P2 & P3, t1 = ~P3 & P4, t2 = ~P4 & P5, t3 = ~P5 & P6;
        uint32_t t4 = ~P6 & P7, t5 = ~P7 & P8, t6 = ~P8 & P9, t7 = ~P9 & P2;
        uint32_t asa = t0 ^ t1 ^ t2, aca = maj3(t0, t1, t2);
        uint32_t asb = t3 ^ t4 ^ t5, acb = maj3(t3, t4, t5);
        uint32_t asc = t6 ^ t7,      acc = t6 & t7;
        uint32_t A0 = asa ^ asb ^ asc;
        uint32_t A1 = maj3(asa, asb, asc);
        uint32_t ex1 = A0 & ~(A1 | aca | acb | acc);

        // ---- c1 & c2 ----
        uint32_t inner;
        if (FIRST) inner = (P4 & P6) & (P2 | P8);
        else       inner = (P2 & P8) & (P4 | P6);

        uint32_t del = ge2 & ~ge7 & ex1 & ~inner;
        o[j] = mi & ~del;
    }

    *(uint4*)(dst + base) = make_uint4(o[0], o[1], o[2], o[3]);
}

// ---------------------------------------------------------------------------
// Unpack: bits -> float 0/1. One thread per pixel; the word load broadcasts
// within each warp, stores fully coalesced.
// ---------------------------------------------------------------------------
__global__ void unpack_kernel(float* __restrict__ out) {
    int tid = blockIdx.x * blockDim.x + threadIdx.x;
    uint32_t w = g_bufA[tid >> 5];
    out[tid] = (float)((w >> (tid & 31)) & 1u);
}

extern "C" void kernel_launch(void* const* d_in, const int* in_sizes, int n_in,
                              void* d_out, int out_size) {
    (void)in_sizes; (void)n_in; (void)out_size;
    const float* in = (const float*)d_in[0];
    float* out = (float*)d_out;

    const int NPIX = NIMG * H * WPX;              // 8388608
    pack_kernel<<<NPIX / 256, 256>>>(in);

    const int NTHREADS = NIMG * H * 4;            // 65536 (4 words / thread)
    for (int it = 0; it < 8; ++it) {
        substep_kernel<true,  true ><<<NTHREADS / 256, 256>>>();  // A -> B
        substep_kernel<false, false><<<NTHREADS / 256, 256>>>();  // B -> A
    }

    unpack_kernel<<<NPIX / 256, 256>>>(out);      // result lives in A
}

// round 2
// speedup vs baseline: 1.0194x; 1.0194x over previous
#include <cuda_runtime.h>
#include <stdint.h>

// Problem shape is fixed: 32 images, 512x512, 1 channel, float32.
#define NIMG 32
#define H    512
#define WPX  512
#define WPR  16                       // 32-bit words per row (512/32)
#define NWORDS (NIMG * H * WPR)       // 262144 words = 1 MB per buffer

// Ping-pong bit buffers (device globals: no allocation allowed).
__device__ uint32_t g_bufA[NWORDS];
__device__ uint32_t g_bufB[NWORDS];

// ---------------------------------------------------------------------------
// Pack: threshold float image to bits. One thread per pixel, warp ballot
// produces one 32-bit word (bit i of word = column base+i). Fully coalesced.
// ---------------------------------------------------------------------------
__global__ void pack_kernel(const float* __restrict__ in) {
    int tid = blockIdx.x * blockDim.x + threadIdx.x;   // pixel index
    float v = in[tid];
    unsigned m = __ballot_sync(0xffffffffu, v >= 0.5f);
    if ((tid & 31) == 0) g_bufA[tid >> 5] = m;
}

__device__ __forceinline__ uint32_t maj3(uint32_t a, uint32_t b, uint32_t c) {
    return (a & b) | (c & (a | b));    // 1 LOP3
}

// ---------------------------------------------------------------------------
// One Zhang-Suen substep on the bit-packed image.
// Thread handles 2 consecutive words (1/8 row): uint2 loads/stores.
// 131072 threads -> 4096 warps (43% occupancy) for latency hiding.
//
// Neighbor masks via funnel shifts; out-of-image neighbors are 0.
// Counts via CSA trees (XOR3 + MAJ3 per full adder).
// ---------------------------------------------------------------------------
template<bool FIRST, bool SRC_A>
__global__ void __launch_bounds__(256) substep_kernel() {
    const uint32_t* __restrict__ src = SRC_A ? g_bufA : g_bufB;
    uint32_t* __restrict__ dst       = SRC_A ? g_bufB : g_bufA;

    int tid  = blockIdx.x * blockDim.x + threadIdx.x;  // 0 .. 131071
    int g    = tid & 7;                                // 2-word group in row
    int rowg = tid >> 3;                               // img*512 + row
    int row  = rowg & (H - 1);
    int base = rowg * WPR + g * 2;

    uint2 um, mm, dm;
    uint32_t ul, ur, ml, mr, dl, dr;

    mm = *(const uint2*)(src + base);
    ml = (g > 0) ? src[base - 1] : 0u;
    mr = (g < 7) ? src[base + 2] : 0u;

    if (row > 0) {
        um = *(const uint2*)(src + base - WPR);
        ul = (g > 0) ? src[base - WPR - 1] : 0u;
        ur = (g < 7) ? src[base - WPR + 2] : 0u;
    } else { um = make_uint2(0, 0); ul = ur = 0u; }

    if (row < H - 1) {
        dm = *(const uint2*)(src + base + WPR);
        dl = (g > 0) ? src[base + WPR - 1] : 0u;
        dr = (g < 7) ? src[base + WPR + 2] : 0u;
    } else { dm = make_uint2(0, 0); dl = dr = 0u; }

    uint32_t u[2] = {um.x, um.y};
    uint32_t m[2] = {mm.x, mm.y};
    uint32_t d[2] = {dm.x, dm.y};
    uint32_t o[2];

    #pragma unroll
    for (int j = 0; j < 2; ++j) {
        uint32_t up = u[j], mi = m[j], dn = d[j];
        uint32_t upl = j ? u[0] : ul, upr = j ? ur : u[1];
        uint32_t mil = j ? m[0] : ml, mir = j ? mr : m[1];
        uint32_t dnl = j ? d[0] : dl, dnr = j ? dr : d[1];

        uint32_t P2 = up;
        uint32_t P3 = __funnelshift_r(up, upr, 1);
        uint32_t P4 = __funnelshift_r(mi, mir, 1);
        uint32_t P5 = __funnelshift_r(dn, dnr, 1);
        uint32_t P6 = dn;
        uint32_t P7 = __funnelshift_l(dnl, dn, 1);
        uint32_t P8 = __funnelshift_l(mil, mi, 1);
        uint32_t P9 = __funnelshift_l(upl, up, 1);

        // ---- bcnt (8 neighbors) via CSA: need 2 <= bcnt <= 6 ----
        uint32_t sa = P2 ^ P3 ^ P4, ca = maj3(P2, P3, P4);
        uint32_t sb = P5 ^ P6 ^ P7, cb = maj3(P5, P6, P7);
        uint32_t sc = P8 ^ P9,      cc = P8 & P9;
        uint32_t S0 = sa ^ sb ^ sc, C1 = maj3(sa, sb, sc);
        uint32_t S1 = ca ^ cb ^ cc, C2 = maj3(ca, cb, cc);
        uint32_t ge2 = C1 | S1 | C2;
        uint32_t ge7 = C2 & ((C1 & S1) | ((C1 ^ S1) & S0));

        // ---- acnt (0->1 transitions around the ring): need == 1 ----
        uint32_t t0 = ~P2 & P3, t1 = ~P3 & P4, t2 = ~P4 & P5, t3 = ~P5 & P6;
        uint32_t t4 = ~P6 & P7, t5 = ~P7 & P8, t6 = ~P8 & P9, t7 = ~P9 & P2;
        uint32_t asa = t0 ^ t1 ^ t2, aca = maj3(t0, t1, t2);
        uint32_t asb = t3 ^ t4 ^ t5, acb = maj3(t3, t4, t5);
        uint32_t asc = t6 ^ t7,      acc = t6 & t7;
        uint32_t A0 = asa ^ asb ^ asc;
        uint32_t A1 = maj3(asa, asb, asc);
        uint32_t ex1 = A0 & ~(A1 | aca | acb | acc);

        // ---- c1 & c2 ----
        uint32_t inner;
        if (FIRST) inner = (P4 & P6) & (P2 | P8);
        else       inner = (P2 & P8) & (P4 | P6);

        uint32_t del = ge2 & ~ge7 & ex1 & ~inner;
        o[j] = mi & ~del;
    }

    *(uint2*)(dst + base) = make_uint2(o[0], o[1]);
}

// ---------------------------------------------------------------------------
// Unpack: bits -> float 0/1. One thread per pixel; the word load broadcasts
// within each warp, stores fully coalesced.
// ---------------------------------------------------------------------------
__global__ void unpack_kernel(float* __restrict__ out) {
    int tid = blockIdx.x * blockDim.x + threadIdx.x;
    uint32_t w = g_bufA[tid >> 5];
    out[tid] = (float)((w >> (tid & 31)) & 1u);
}

extern "C" void kernel_launch(void* const* d_in, const int* in_sizes, int n_in,
                              void* d_out, int out_size) {
    (void)in_sizes; (void)n_in; (void)out_size;
    const float* in = (const float*)d_in[0];
    float* out = (float*)d_out;

    const int NPIX = NIMG * H * WPX;              // 8388608
    pack_kernel<<<NPIX / 256, 256>>>(in);

    const int NTHREADS = NIMG * H * 8;            // 131072 (2 words / thread)
    for (int it = 0; it < 8; ++it) {
        substep_kernel<true,  true ><<<NTHREADS / 256, 256>>>();  // A -> B
        substep_kernel<false, false><<<NTHREADS / 256, 256>>>();  // B -> A
    }

    unpack_kernel<<<NPIX / 256, 256>>>(out);      // result lives in A
}

// round 3
// speedup vs baseline: 1.2329x; 1.2094x over previous
#include <cuda_runtime.h>
#include <stdint.h>

// Problem shape is fixed: 32 images, 512x512, 1 channel, float32.
#define NIMG 32
#define H    512
#define WPX  512
#define WPR  16                       // 32-bit words per row (512/32)
#define NWORDS (NIMG * H * WPR)       // 262144 words = 1 MB
#define SEGROWS 128                   // rows per CTA (H / CLUSTER)
#define CLUSTER 4
#define TPB 256

// Packed bit buffer (device global: no allocation allowed).
__device__ uint32_t g_bufA[NWORDS];

// ---------------------------------------------------------------------------
// Pack: threshold float image to bits via warp ballot. Fully coalesced.
// ---------------------------------------------------------------------------
__global__ void pack_kernel(const float* __restrict__ in) {
    int tid = blockIdx.x * blockDim.x + threadIdx.x;   // pixel index
    float v = in[tid];
    unsigned m = __ballot_sync(0xffffffffu, v >= 0.5f);
    if ((tid & 31) == 0) g_bufA[tid >> 5] = m;
}

// ---------------------------------------------------------------------------
// Unpack: bits -> float 0/1.
// ---------------------------------------------------------------------------
__global__ void unpack_kernel(float* __restrict__ out) {
    int tid = blockIdx.x * blockDim.x + threadIdx.x;
    uint32_t w = g_bufA[tid >> 5];
    out[tid] = (float)((w >> (tid & 31)) & 1u);
}

__device__ __forceinline__ uint32_t maj3(uint32_t a, uint32_t b, uint32_t c) {
    return (a & b) | (c & (a | b));    // 1 LOP3
}

// DSMEM read of a shared-memory word from cluster CTA `rank`.
__device__ __forceinline__ uint32_t dsmem_ld(const uint32_t* p, uint32_t rank) {
    uint32_t a = (uint32_t)__cvta_generic_to_shared(p);
    uint32_t ra, v;
    asm volatile("mapa.shared::cluster.u32 %0, %1, %2;" : "=r"(ra) : "r"(a), "r"(rank));
    asm volatile("ld.shared::cluster.u32 %0, [%1];" : "=r"(v) : "r"(ra));
    return v;
}

__device__ __forceinline__ void cluster_barrier() {
    asm volatile("barrier.cluster.arrive.aligned;" ::: "memory");
    asm volatile("barrier.cluster.wait.aligned;" ::: "memory");
}

// Zhang-Suen delete mask for one 32-pixel word, given the 8 neighbor masks.
// acnt==1 is computed as acnt<=1, valid because 2<=bcnt<=6 implies acnt>=1.
template<bool FIRST>
__device__ __forceinline__ uint32_t word_update(
    uint32_t mi, uint32_t P2, uint32_t P3, uint32_t P4, uint32_t P5,
    uint32_t P6, uint32_t P7, uint32_t P8, uint32_t P9)
{
    // ---- bcnt via CSA: need 2 <= bcnt <= 6 ----
    uint32_t sa = P2 ^ P3 ^ P4, ca = maj3(P2, P3, P4);
    uint32_t sb = P5 ^ P6 ^ P7, cb = maj3(P5, P6, P7);
    uint32_t sc = P8 ^ P9,      cc = P8 & P9;
    uint32_t S0 = sa ^ sb ^ sc, C1 = maj3(sa, sb, sc);
    uint32_t S1 = ca ^ cb ^ cc, C2 = maj3(ca, cb, cc);
    uint32_t ge2 = C1 | S1 | C2;
    uint32_t ge7 = C2 & ((C1 & S1) | ((C1 ^ S1) & S0));

    // ---- acnt <= 1: no weight-2 terms in the transition CSA ----
    uint32_t t0 = ~P2 & P3, t1 = ~P3 & P4, t2 = ~P4 & P5, t3 = ~P5 & P6;
    uint32_t t4 = ~P6 & P7, t5 = ~P7 & P8, t6 = ~P8 & P9, t7 = ~P9 & P2;
    uint32_t aca = maj3(t0, t1, t2);
    uint32_t acb = maj3(t3, t4, t5);
    uint32_t acc = t6 & t7;
    uint32_t asa = t0 ^ t1 ^ t2;
    uint32_t asb = t3 ^ t4 ^ t5;
    uint32_t asc = t6 ^ t7;
    uint32_t A1  = maj3(asa, asb, asc);
    uint32_t ex1 = ~(A1 | aca | acb) & ~acc;

    // ---- c1 & c2 ----
    uint32_t inner;
    if (FIRST) inner = (P4 & P6) & (P2 | P8);
    else       inner = (P2 & P8) & (P4 | P6);

    uint32_t del = ge2 & ~ge7 & ex1 & ~inner;
    return mi & ~del;
}

// One substep: cluster sync, halo exchange (src buffer), compute src -> dst.
// Shared buffer layout: 130 rows x 16 words; local row r at index (r+1)*WPR.
template<bool FIRST>
__device__ __forceinline__ void do_substep(
    const uint32_t* __restrict__ S, uint32_t* __restrict__ Dst,
    int rank, int tid)
{
    cluster_barrier();   // all CTAs' S complete cluster-wide

    // Halo exchange: top halo (row index 0) from rank-1's local row 127,
    // bottom halo (row index 129) from rank+1's local row 0.
    if (tid < WPR) {
        uint32_t v = 0;
        if (rank > 0) v = dsmem_ld(&S[SEGROWS * WPR + tid], (uint32_t)(rank - 1));
        ((uint32_t*)S)[tid] = v;
    } else if (tid < 2 * WPR) {
        int w = tid - WPR;
        uint32_t v = 0;
        if (rank < CLUSTER - 1) v = dsmem_ld(&S[WPR + w], (uint32_t)(rank + 1));
        ((uint32_t*)S)[(SEGROWS + 1) * WPR + w] = v;
    }
    __syncthreads();

    // Each thread: one half-row strip of 8 words.
    int r  = tid >> 1;
    int h2 = tid & 1;
    int base = (r + 1) * WPR + h2 * 8;

    uint4 m0 = *(const uint4*)&S[base],       m1 = *(const uint4*)&S[base + 4];
    uint4 u0 = *(const uint4*)&S[base - WPR], u1 = *(const uint4*)&S[base - WPR + 4];
    uint4 d0 = *(const uint4*)&S[base + WPR], d1 = *(const uint4*)&S[base + WPR + 4];
    uint32_t ml = h2 ? S[base - 1]       : 0u, mr = h2 ? 0u : S[base + 8];
    uint32_t ul = h2 ? S[base - WPR - 1] : 0u, ur = h2 ? 0u : S[base - WPR + 8];
    uint32_t dl = h2 ? S[base + WPR - 1] : 0u, dr = h2 ? 0u : S[base + WPR + 8];

    uint32_t u[8] = {u0.x, u0.y, u0.z, u0.w, u1.x, u1.y, u1.z, u1.w};
    uint32_t m[8] = {m0.x, m0.y, m0.z, m0.w, m1.x, m1.y, m1.z, m1.w};
    uint32_t d[8] = {d0.x, d0.y, d0.z, d0.w, d1.x, d1.y, d1.z, d1.w};
    uint32_t o[8];

    #pragma unroll
    for (int j = 0; j < 8; ++j) {
        uint32_t up = u[j], mi = m[j], dn = d[j];
        uint32_t upl = j ? u[j - 1] : ul, upr = (j < 7) ? u[j + 1] : ur;
        uint32_t mil = j ? m[j - 1] : ml, mir = (j < 7) ? m[j + 1] : mr;
        uint32_t dnl = j ? d[j - 1] : dl, dnr = (j < 7) ? d[j + 1] : dr;

        uint32_t P2 = up;
        uint32_t P3 = __funnelshift_r(up, upr, 1);
        uint32_t P4 = __funnelshift_r(mi, mir, 1);
        uint32_t P5 = __funnelshift_r(dn, dnr, 1);
        uint32_t P6 = dn;
        uint32_t P7 = __funnelshift_l(dnl, dn, 1);
        uint32_t P8 = __funnelshift_l(mil, mi, 1);
        uint32_t P9 = __funnelshift_l(upl, up, 1);

        o[j] = word_update<FIRST>(mi, P2, P3, P4, P5, P6, P7, P8, P9);
    }

    *(uint4*)&Dst[base]     = make_uint4(o[0], o[1], o[2], o[3]);
    *(uint4*)&Dst[base + 4] = make_uint4(o[4], o[5], o[6], o[7]);
}

// ---------------------------------------------------------------------------
// Persistent cluster kernel: all 16 substeps for one image segment.
// Grid = 128 CTAs (32 images x 4 segments), cluster = 4 CTAs (one image).
// ---------------------------------------------------------------------------
__global__ void __cluster_dims__(CLUSTER, 1, 1) __launch_bounds__(TPB, 1)
skeleton_cluster_kernel() {
    __shared__ uint32_t sb[2][(SEGROWS + 2) * WPR];   // double buffer + halos

    int tid   = threadIdx.x;
    int rank  = blockIdx.x & (CLUSTER - 1);
    int gbase = blockIdx.x * (SEGROWS * WPR);         // img*8192 + seg*2048

    // Load own 2048 words into sb[0] rows 1..128 (coalesced uint4).
    {
        uint4* dst4 = (uint4*)&sb[0][WPR];
        const uint4* src4 = (const uint4*)&g_bufA[gbase];
        dst4[tid]       = src4[tid];
        dst4[tid + TPB] = src4[tid + TPB];
    }
    // cluster_barrier inside the first do_substep orders these writes
    // before any remote halo read.

    #pragma unroll 1
    for (int it = 0; it < 8; ++it) {
        do_substep<true >(sb[0], sb[1], rank, tid);
        do_substep<false>(sb[1], sb[0], rank, tid);
    }

    // Ensure no neighbor still needs our smem, and own writes are done.
    cluster_barrier();

    // Write back sb[0] rows 1..128.
    {
        const uint4* src4 = (const uint4*)&sb[0][WPR];
        uint4* dst4 = (uint4*)&g_bufA[gbase];
        dst4[tid]       = src4[tid];
        dst4[tid + TPB] = src4[tid + TPB];
    }
}

extern "C" void kernel_launch(void* const* d_in, const int* in_sizes, int n_in,
                              void* d_out, int out_size) {
    (void)in_sizes; (void)n_in; (void)out_size;
    const float* in = (const float*)d_in[0];
    float* out = (float*)d_out;

    const int NPIX = NIMG * H * WPX;              // 8388608
    pack_kernel<<<NPIX / 256, 256>>>(in);

    skeleton_cluster_kernel<<<NIMG * CLUSTER, TPB>>>();

    unpack_kernel<<<NPIX / 256, 256>>>(out);
}

// round 4
// speedup vs baseline: 2.0925x; 1.6972x over previous
#include <cuda_runtime.h>
#include <stdint.h>

// Problem shape is fixed: 32 images, 512x512, 1 channel, float32.
#define NIMG 32
#define H    512
#define WPX  512
#define WPR  16                       // 32-bit words per row (512/32)
#define NWORDS (NIMG * H * WPR)       // 262144 words = 1 MB
#define SEGROWS 128                   // rows per CTA (H / CLUSTER)
#define CLUSTER 4
#define TPB 256

// Packed bit buffer (device global: no allocation allowed).
__device__ uint32_t g_bufA[NWORDS];

// ---------------------------------------------------------------------------
// Pack v2: one warp -> 256 pixels -> 8 words. 8 independent coalesced loads
// per thread (MLP=8), 8 ballots (results are warp-uniform), lane 0 stores the
// 8 words as two STG.128.
// ---------------------------------------------------------------------------
__global__ void __launch_bounds__(256) pack_kernel(const float* __restrict__ in) {
    int warpId = (blockIdx.x * blockDim.x + threadIdx.x) >> 5;
    int lane   = threadIdx.x & 31;
    int pbase  = warpId * 256;                 // pixel base for this warp

    float v[8];
    #pragma unroll
    for (int j = 0; j < 8; ++j) v[j] = in[pbase + j * 32 + lane];

    uint32_t b[8];
    #pragma unroll
    for (int j = 0; j < 8; ++j) b[j] = __ballot_sync(0xffffffffu, v[j] >= 0.5f);

    if (lane == 0) {
        int wbase = pbase >> 5;
        *(uint4*)&g_bufA[wbase]     = make_uint4(b[0], b[1], b[2], b[3]);
        *(uint4*)&g_bufA[wbase + 4] = make_uint4(b[4], b[5], b[6], b[7]);
    }
}

// ---------------------------------------------------------------------------
// Unpack v2: one thread -> 4 pixels via STG.128. Word load broadcasts
// within each group of 8 lanes.
// ---------------------------------------------------------------------------
__global__ void __launch_bounds__(256) unpack_kernel(float* __restrict__ out) {
    int tid = blockIdx.x * blockDim.x + threadIdx.x;   // 0 .. NPIX/4-1
    uint32_t w = g_bufA[tid >> 3];
    int sh = (tid & 7) * 4;
    float4 f;
    f.x = (float)((w >> (sh + 0)) & 1u);
    f.y = (float)((w >> (sh + 1)) & 1u);
    f.z = (float)((w >> (sh + 2)) & 1u);
    f.w = (float)((w >> (sh + 3)) & 1u);
    *(float4*)&out[tid * 4] = f;
}

__device__ __forceinline__ uint32_t maj3(uint32_t a, uint32_t b, uint32_t c) {
    return (a & b) | (c & (a | b));    // 1 LOP3
}

// DSMEM read of a shared-memory word from cluster CTA `rank`.
__device__ __forceinline__ uint32_t dsmem_ld(const uint32_t* p, uint32_t rank) {
    uint32_t a = (uint32_t)__cvta_generic_to_shared(p);
    uint32_t ra, v;
    asm volatile("mapa.shared::cluster.u32 %0, %1, %2;" : "=r"(ra) : "r"(a), "r"(rank));
    asm volatile("ld.shared::cluster.u32 %0, [%1];" : "=r"(v) : "r"(ra));
    return v;
}

__device__ __forceinline__ void cluster_barrier() {
    asm volatile("barrier.cluster.arrive.aligned;" ::: "memory");
    asm volatile("barrier.cluster.wait.aligned;" ::: "memory");
}

// Zhang-Suen delete mask for one 32-pixel word, given the 8 neighbor masks.
// acnt==1 is computed as acnt<=1, valid because 2<=bcnt<=6 implies acnt>=1.
template<bool FIRST>
__device__ __forceinline__ uint32_t word_update(
    uint32_t mi, uint32_t P2, uint32_t P3, uint32_t P4, uint32_t P5,
    uint32_t P6, uint32_t P7, uint32_t P8, uint32_t P9)
{
    // ---- bcnt via CSA: need 2 <= bcnt <= 6 ----
    uint32_t sa = P2 ^ P3 ^ P4, ca = maj3(P2, P3, P4);
    uint32_t sb = P5 ^ P6 ^ P7, cb = maj3(P5, P6, P7);
    uint32_t sc = P8 ^ P9,      cc = P8 & P9;
    uint32_t S0 = sa ^ sb ^ sc, C1 = maj3(sa, sb, sc);
    uint32_t S1 = ca ^ cb ^ cc, C2 = maj3(ca, cb, cc);
    uint32_t ge2 = C1 | S1 | C2;
    uint32_t ge7 = C2 & ((C1 & S1) | ((C1 ^ S1) & S0));

    // ---- acnt <= 1: no weight-2 terms in the transition CSA ----
    uint32_t t0 = ~P2 & P3, t1 = ~P3 & P4, t2 = ~P4 & P5, t3 = ~P5 & P6;
    uint32_t t4 = ~P6 & P7, t5 = ~P7 & P8, t6 = ~P8 & P9, t7 = ~P9 & P2;
    uint32_t aca = maj3(t0, t1, t2);
    uint32_t acb = maj3(t3, t4, t5);
    uint32_t acc = t6 & t7;
    uint32_t asa = t0 ^ t1 ^ t2;
    uint32_t asb = t3 ^ t4 ^ t5;
    uint32_t asc = t6 ^ t7;
    uint32_t A1  = maj3(asa, asb, asc);
    uint32_t ex1 = ~(A1 | aca | acb) & ~acc;

    // ---- c1 & c2 ----
    uint32_t inner;
    if (FIRST) inner = (P4 & P6) & (P2 | P8);
    else       inner = (P2 & P8) & (P4 | P6);

    uint32_t del = ge2 & ~ge7 & ex1 & ~inner;
    return mi & ~del;
}

// One substep: cluster sync, halo exchange (src buffer), compute src -> dst.
// Shared buffer layout: 130 rows x 16 words; local row r at index (r+1)*WPR.
template<bool FIRST>
__device__ __forceinline__ void do_substep(
    const uint32_t* __restrict__ S, uint32_t* __restrict__ Dst,
    int rank, int tid)
{
    cluster_barrier();   // all CTAs' S complete cluster-wide

    // Halo exchange: top halo (row index 0) from rank-1's local row 127,
    // bottom halo (row index 129) from rank+1's local row 0.
    if (tid < WPR) {
        uint32_t v = 0;
        if (rank > 0) v = dsmem_ld(&S[SEGROWS * WPR + tid], (uint32_t)(rank - 1));
        ((uint32_t*)S)[tid] = v;
    } else if (tid < 2 * WPR) {
        int w = tid - WPR;
        uint32_t v = 0;
        if (rank < CLUSTER - 1) v = dsmem_ld(&S[WPR + w], (uint32_t)(rank + 1));
        ((uint32_t*)S)[(SEGROWS + 1) * WPR + w] = v;
    }
    __syncthreads();

    // Each thread: one half-row strip of 8 words.
    int r  = tid >> 1;
    int h2 = tid & 1;
    int base = (r + 1) * WPR + h2 * 8;

    uint4 m0 = *(const uint4*)&S[base],       m1 = *(const uint4*)&S[base + 4];
    uint4 u0 = *(const uint4*)&S[base - WPR], u1 = *(const uint4*)&S[base - WPR + 4];
    uint4 d0 = *(const uint4*)&S[base + WPR], d1 = *(const uint4*)&S[base + WPR + 4];
    uint32_t ml = h2 ? S[base - 1]       : 0u, mr = h2 ? 0u : S[base + 8];
    uint32_t ul = h2 ? S[base - WPR - 1] : 0u, ur = h2 ? 0u : S[base - WPR + 8];
    uint32_t dl = h2 ? S[base + WPR - 1] : 0u, dr = h2 ? 0u : S[base + WPR + 8];

    uint32_t u[8] = {u0.x, u0.y, u0.z, u0.w, u1.x, u1.y, u1.z, u1.w};
    uint32_t m[8] = {m0.x, m0.y, m0.z, m0.w, m1.x, m1.y, m1.z, m1.w};
    uint32_t d[8] = {d0.x, d0.y, d0.z, d0.w, d1.x, d1.y, d1.z, d1.w};
    uint32_t o[8];

    #pragma unroll
    for (int j = 0; j < 8; ++j) {
        uint32_t up = u[j], mi = m[j], dn = d[j];
        uint32_t upl = j ? u[j - 1] : ul, upr = (j < 7) ? u[j + 1] : ur;
        uint32_t mil = j ? m[j - 1] : ml, mir = (j < 7) ? m[j + 1] : mr;
        uint32_t dnl = j ? d[j - 1] : dl, dnr = (j < 7) ? d[j + 1] : dr;

        uint32_t P2 = up;
        uint32_t P3 = __funnelshift_r(up, upr, 1);
        uint32_t P4 = __funnelshift_r(mi, mir, 1);
        uint32_t P5 = __funnelshift_r(dn, dnr, 1);
        uint32_t P6 = dn;
        uint32_t P7 = __funnelshift_l(dnl, dn, 1);
        uint32_t P8 = __funnelshift_l(mil, mi, 1);
        uint32_t P9 = __funnelshift_l(upl, up, 1);

        o[j] = word_update<FIRST>(mi, P2, P3, P4, P5, P6, P7, P8, P9);
    }

    *(uint4*)&Dst[base]     = make_uint4(o[0], o[1], o[2], o[3]);
    *(uint4*)&Dst[base + 4] = make_uint4(o[4], o[5], o[6], o[7]);
}

// ---------------------------------------------------------------------------
// Persistent cluster kernel: all 16 substeps for one image segment.
// Grid = 128 CTAs (32 images x 4 segments), cluster = 4 CTAs (one image).
// ---------------------------------------------------------------------------
__global__ void __cluster_dims__(CLUSTER, 1, 1) __launch_bounds__(TPB, 1)
skeleton_cluster_kernel() {
    __shared__ uint32_t sb[2][(SEGROWS + 2) * WPR];   // double buffer + halos

    int tid   = threadIdx.x;
    int rank  = blockIdx.x & (CLUSTER - 1);
    int gbase = blockIdx.x * (SEGROWS * WPR);         // img*8192 + seg*2048

    // Load own 2048 words into sb[0] rows 1..128 (coalesced uint4).
    {
        uint4* dst4 = (uint4*)&sb[0][WPR];
        const uint4* src4 = (const uint4*)&g_bufA[gbase];
        dst4[tid]       = src4[tid];
        dst4[tid + TPB] = src4[tid + TPB];
    }
    // cluster_barrier inside the first do_substep orders these writes
    // before any remote halo read.

    #pragma unroll 1
    for (int it = 0; it < 8; ++it) {
        do_substep<true >(sb[0], sb[1], rank, tid);
        do_substep<false>(sb[1], sb[0], rank, tid);
    }

    // Ensure no neighbor still needs our smem, and own writes are done.
    cluster_barrier();

    // Write back sb[0] rows 1..128.
    {
        const uint4* src4 = (const uint4*)&sb[0][WPR];
        uint4* dst4 = (uint4*)&g_bufA[gbase];
        dst4[tid]       = src4[tid];
        dst4[tid + TPB] = src4[tid + TPB];
    }
}

extern "C" void kernel_launch(void* const* d_in, const int* in_sizes, int n_in,
                              void* d_out, int out_size) {
    (void)in_sizes; (void)n_in; (void)out_size;
    const float* in = (const float*)d_in[0];
    float* out = (float*)d_out;

    const int NPIX = NIMG * H * WPX;              // 8388608
    pack_kernel<<<NPIX / (256 * 8), 256>>>(in);   // 8 px/thread

    skeleton_cluster_kernel<<<NIMG * CLUSTER, TPB>>>();

    unpack_kernel<<<NPIX / (256 * 4), 256>>>(out); // 4 px/thread
}